// round 2
// baseline (speedup 1.0000x reference)
#include <cuda_runtime.h>
#include <math.h>
#include <math_constants.h>

#define NS 4760
#define KNN 16
#define NB 16
#define NT 6

// ------------------------- device scratch -------------------------
__device__ float g_ql [NS*64];
__device__ float g_sp [NS*64];
__device__ float g_spW[NS*64];
__device__ float g_qg [NS*128];
__device__ float g_a0 [NS];
__device__ float g_a1 [NS];
__device__ float g_kg [NB*NT*128];
__device__ float g_vgo [NB*25*128];
__device__ float g_vgoW[NB*25*64];
__device__ float g_sumv[NB*25];
__device__ float g_gram[NB*25*25];
__device__ float g_gl  [(size_t)NS*NB*24];
__device__ float g_cst [256];   // [w0W(64) w1W(64) gcol(64) cadd(64)]

__device__ __forceinline__ float wsum(float v){
    #pragma unroll
    for (int o=16;o;o>>=1) v += __shfl_xor_sync(0xffffffffu, v, o);
    return v;
}
__device__ __forceinline__ float wmax(float v){
    #pragma unroll
    for (int o=16;o;o>>=1) v = fmaxf(v, __shfl_xor_sync(0xffffffffu, v, o));
    return v;
}

// ------------------------- K consts -------------------------
__global__ void k_consts(const float* __restrict__ Wnbr, const float* __restrict__ lng,
                         const float* __restrict__ lnb, const float* __restrict__ Wm1,
                         const float* __restrict__ bm1){
    int j = threadIdx.x;   // 64
    float w0W=0.f, w1W=0.f, gcol=0.f, cadd=0.f;
    for (int i=0;i<192;i++){
        float w = Wm1[i*64+j];
        gcol += lng[i]*w;
        cadd += lnb[i]*w;
    }
    for (int i=0;i<64;i++){
        float w = lng[i]*Wm1[i*64+j];
        w0W += Wnbr[i]     * w;
        w1W += Wnbr[64+i]  * w;
    }
    g_cst[j]      = w0W;
    g_cst[64+j]   = w1W;
    g_cst[128+j]  = gcol;
    g_cst[192+j]  = cadd + bm1[j];
}

// ------------------------- K A: sensor static -------------------------
// per sensor: ql = query@W_ql+b_ql ; sp = query@W_nbr[2:]+b_nbr ; qg = query@W_qg+b_qg
// spW = sp@W1g_top ; a0 = w0.ql ; a1 = w1.ql
#define A_TS 32
__global__ void __launch_bounds__(256,1) kA(
    const float* __restrict__ pos, const float* __restrict__ femb, const int* __restrict__ fid,
    const float* __restrict__ Wnbr, const float* __restrict__ bnbr,
    const float* __restrict__ Wql,  const float* __restrict__ bql,
    const float* __restrict__ Wqg,  const float* __restrict__ bqg,
    const float* __restrict__ lng,  const float* __restrict__ Wm1)
{
    extern __shared__ float sm[];
    float* sWql = sm;              // 8192
    float* sWnb = sm + 8192;       // 8192
    float* sWqg = sm + 16384;      // 16384
    float* sW1t = sm + 32768;      // 4096
    float* sQ   = sm + 36864;      // 32*128
    float* sSP  = sm + 40960;      // 32*64
    float* sQL  = sm + 43008;      // 32*64  (total 45056 floats)
    int tid = threadIdx.x;
    int n0 = blockIdx.x * A_TS;

    for (int e=tid;e<8192;e+=256){ sWql[e]=Wql[e]; sWnb[e]=Wnbr[128+e]; }
    for (int e=tid;e<16384;e+=256) sWqg[e]=Wqg[e];
    for (int e=tid;e<4096;e+=256)  sW1t[e]=lng[e>>6]*Wm1[e];
    for (int e=tid;e<4096;e+=256){
        int s=e>>7, i=e&127, n=n0+s;
        float v=0.f;
        if (n<NS) v = (i<96) ? pos[n*96+i] : femb[fid[n]*32 + (i-96)];
        sQ[e]=v;
    }
    __syncthreads();

    int c4 = (tid & 63)*4;       // col group of 4 in [0,256)
    int sbase = (tid >> 6)*8;    // 8 sensors
    const float* Wp; int ld, cc;
    if (c4 < 64)       { Wp=sWql; ld=64;  cc=c4; }
    else if (c4 < 128) { Wp=sWnb; ld=64;  cc=c4-64; }
    else               { Wp=sWqg; ld=128; cc=c4-128; }

    float acc[8][4];
    #pragma unroll
    for (int s=0;s<8;s++){ acc[s][0]=0.f; acc[s][1]=0.f; acc[s][2]=0.f; acc[s][3]=0.f; }

    for (int i=0;i<128;i++){
        float4 w = *(const float4*)(Wp + i*ld + cc);
        #pragma unroll
        for (int s=0;s<8;s++){
            float q = sQ[(sbase+s)*128 + i];
            acc[s][0] = fmaf(q, w.x, acc[s][0]);
            acc[s][1] = fmaf(q, w.y, acc[s][1]);
            acc[s][2] = fmaf(q, w.z, acc[s][2]);
            acc[s][3] = fmaf(q, w.w, acc[s][3]);
        }
    }
    #pragma unroll
    for (int u=0;u<4;u++){
        int col = c4+u;
        float bias;
        if (col<64) bias = bql[col];
        else if (col<128) bias = bnbr[col-64];
        else bias = bqg[col-128];
        #pragma unroll
        for (int s=0;s<8;s++){
            int n = n0 + sbase + s;
            float v = acc[s][u] + bias;
            if (col<64)       sQL[(sbase+s)*64+col]      = v;
            else if (col<128) sSP[(sbase+s)*64+(col-64)] = v;
            if (n < NS){
                if (col<64)       g_ql[n*64+col]        = v;
                else if (col<128) g_sp[n*64+(col-64)]   = v;
                else              g_qg[n*128+(col-128)] = v;
            }
        }
    }
    __syncthreads();

    // spW = sp @ W1g_top
    {
        int j4 = (tid & 15)*4;
        int s0 = (tid >> 4)*2;
        float a0_=0.f,a1_=0.f,a2_=0.f,a3_=0.f,b0_=0.f,b1_=0.f,b2_=0.f,b3_=0.f;
        for (int i=0;i<64;i++){
            float4 w = *(const float4*)(sW1t + i*64 + j4);
            float q0 = sSP[s0*64+i], q1 = sSP[(s0+1)*64+i];
            a0_=fmaf(q0,w.x,a0_); a1_=fmaf(q0,w.y,a1_); a2_=fmaf(q0,w.z,a2_); a3_=fmaf(q0,w.w,a3_);
            b0_=fmaf(q1,w.x,b0_); b1_=fmaf(q1,w.y,b1_); b2_=fmaf(q1,w.z,b2_); b3_=fmaf(q1,w.w,b3_);
        }
        int na = n0+s0, nb2 = n0+s0+1;
        if (na<NS){ g_spW[na*64+j4]=a0_; g_spW[na*64+j4+1]=a1_; g_spW[na*64+j4+2]=a2_; g_spW[na*64+j4+3]=a3_; }
        if (nb2<NS){ g_spW[nb2*64+j4]=b0_; g_spW[nb2*64+j4+1]=b1_; g_spW[nb2*64+j4+2]=b2_; g_spW[nb2*64+j4+3]=b3_; }
    }
    // a0/a1
    if (tid < 32){
        int n = n0 + tid;
        if (n < NS){
            float a0=0.f, a1=0.f;
            for (int i=0;i<64;i++){
                float q = sQL[tid*64+i];
                a0 = fmaf(Wnbr[i],    q, a0);
                a1 = fmaf(Wnbr[64+i], q, a1);
            }
            g_a0[n]=a0; g_a1[n]=a1;
        }
    }
}

// ------------------------- K D: per (b,t) latent path -------------------------
__global__ void __launch_bounds__(128,1) kD(
    const float* __restrict__ latent, const float* __restrict__ femb,
    const float* __restrict__ Wlat, const float* __restrict__ blat,
    const float* __restrict__ Wlf,  const float* __restrict__ blf,
    const float* __restrict__ Wk,   const float* __restrict__ bk,
    const float* __restrict__ Wv,   const float* __restrict__ bv,
    const float* __restrict__ Wgo,  const float* __restrict__ bgo)
{
    __shared__ float lat_s[1024], face_s[32], kv_s[128], vg_s[128];
    int t = blockIdx.x, b = blockIdx.y, tid = threadIdx.x;
    for (int e=tid;e<1024;e+=128) lat_s[e] = latent[((size_t)b*NT+t)*1024 + e];
    if (tid<32) face_s[tid] = femb[t*32+tid];
    __syncthreads();
    int j = tid;
    float kv = blat[j] + blf[j];
    for (int i=0;i<1024;i++) kv = fmaf(lat_s[i], Wlat[i*128+j], kv);
    for (int i=0;i<32;i++)   kv = fmaf(face_s[i], Wlf[i*128+j], kv);
    kv_s[j] = kv;
    __syncthreads();
    float kg = bk[j], vg = bv[j];
    for (int i=0;i<128;i++){
        float c = kv_s[i];
        kg = fmaf(c, Wk[i*128+j], kg);
        vg = fmaf(c, Wv[i*128+j], vg);
    }
    g_kg[(b*NT+t)*128 + j] = kg;
    vg_s[j] = vg;
    __syncthreads();
    #pragma unroll
    for (int h=0;h<4;h++){
        float a = 0.f;
        for (int d=0;d<32;d++) a = fmaf(vg_s[h*32+d], Wgo[(h*32+d)*128+j], a);
        g_vgo[((size_t)b*25 + t*4 + h)*128 + j] = a;
    }
    if (t==0) g_vgo[((size_t)b*25 + 24)*128 + j] = bgo[j];
}

// ------------------------- K E: per-batch folds -------------------------
__global__ void __launch_bounds__(256,1) kE(const float* __restrict__ lng, const float* __restrict__ Wm1){
    extern __shared__ float sm[];
    float* vgo_s = sm;          // 25*129
    float* w1b   = sm + 3225;   // 128*64
    int b = blockIdx.x, tid = threadIdx.x;
    for (int e=tid;e<3200;e+=256){ int i=e>>7, c=e&127; vgo_s[i*129+c] = g_vgo[(size_t)b*3200+e]; }
    for (int e=tid;e<8192;e+=256){ int c=e>>6; w1b[e] = lng[64+c]*Wm1[(64+c)*64 + (e&63)]; }
    __syncthreads();
    int j = tid & 63, i0 = tid >> 6;
    for (int i=i0;i<25;i+=4){
        float acc = 0.f;
        for (int c=0;c<128;c++) acc = fmaf(vgo_s[i*129+c], w1b[c*64+j], acc);
        g_vgoW[(b*25+i)*64 + j] = acc;
    }
    if (tid < 25){
        float s = 0.f;
        for (int c=0;c<128;c++) s += vgo_s[tid*129+c];
        g_sumv[b*25+tid] = s;
    }
    for (int p=tid;p<625;p+=256){
        int i1=p/25, i2=p%25;
        float s = 0.f;
        for (int c=0;c<128;c++) s = fmaf(vgo_s[i1*129+c], vgo_s[i2*129+c], s);
        g_gram[b*625+p] = s;
    }
}

// ------------------------- K F: global logits -------------------------
__global__ void __launch_bounds__(512,1) kF(){
    extern __shared__ float kgs[];   // 384 rows * 33
    int tid = threadIdx.x;
    for (int e=tid;e<NB*NT*128;e+=512){
        int b=e/768, r=e%768, t=r/128, q=r%128, h=q>>5, d=q&31;
        kgs[(b*24 + t*4 + h)*33 + d] = g_kg[e];
    }
    __syncthreads();
    int wid = tid >> 5, lane = tid & 31;
    int h = lane/6, t = lane%6;
    for (int n = blockIdx.x*16 + wid; n < NS; n += gridDim.x*16){
        float q[32];
        if (lane < 24){
            #pragma unroll
            for (int d=0;d<32;d++) q[d] = g_qg[n*128 + h*32 + d];
            for (int b=0;b<16;b++){
                int row = b*24 + t*4 + h;
                float acc = 0.f;
                #pragma unroll
                for (int d=0;d<32;d++) acc = fmaf(q[d], kgs[row*33+d], acc);
                g_gl[((size_t)n*16 + b)*24 + lane] = acc * 0.17677669529663687f;
            }
        }
    }
}

// ------------------------- K G: fused main -------------------------
__global__ void __launch_bounds__(512,1) kG(
    const float* __restrict__ xf, const int* __restrict__ mask, const int* __restrict__ knn,
    const float* __restrict__ Wnbr, const float* __restrict__ Wm2, const float* __restrict__ bm2,
    float* __restrict__ out)
{
    extern __shared__ float sm[];
    float* vgoW_s = sm;            // 25600
    float* gram_s = sm + 25600;    // 10000
    float* sumv_s = sm + 35600;    // 400
    float* cst    = sm + 36000;    // 448
    int tid = threadIdx.x;
    for (int e=tid;e<25600;e+=512) vgoW_s[e] = g_vgoW[e];
    for (int e=tid;e<10000;e+=512) gram_s[e] = g_gram[e];
    if (tid < 400) sumv_s[tid] = g_sumv[tid];
    if (tid < 128) cst[tid] = Wnbr[tid];                 // w0 | w1
    if (tid >= 128 && tid < 384) cst[tid] = g_cst[tid-128]; // w0W w1W gcol cadd
    if (tid >= 384 && tid < 448) cst[tid] = Wm2[tid-384];
    __syncthreads();
    const float* w0_s  = cst;
    const float* w1_s  = cst + 64;
    const float* w0W_s = cst + 128;
    const float* w1W_s = cst + 192;
    const float* gcol_s= cst + 256;
    const float* cadd_s= cst + 320;
    const float* wm2_s = cst + 384;

    const unsigned FULL = 0xffffffffu;
    int wid = tid >> 5, lane = tid & 31;
    float bm2v = bm2[0];

    for (int n = blockIdx.x*16 + wid; n < NS; n += gridDim.x*16){
        int kj = 0;
        if (lane < 16) kj = knn[n*16 + lane];
        float a0 = g_a0[n], a1 = g_a1[n];
        float ql0 = g_ql[n*64 + lane], ql1 = g_ql[n*64 + 32 + lane];
        float rsp0[16], rsp1[16], rw0[16], rw1[16];
        #pragma unroll
        for (int k=0;k<16;k++){
            int j = __shfl_sync(FULL, kj, k);
            rsp0[k] = g_sp[j*64 + lane];
            rsp1[k] = g_sp[j*64 + 32 + lane];
            rw0[k]  = g_spW[j*64 + lane];
            rw1[k]  = g_spW[j*64 + 32 + lane];
        }
        float Sreg = 0.f;
        #pragma unroll
        for (int k=0;k<16;k++){
            float p = fmaf(rsp0[k], ql0, rsp1[k]*ql1);
            p = wsum(p);
            if (lane == k) Sreg = p;
        }

        for (int b=0;b<16;b++){
            // ---- local attention ----
            float x0 = 0.f, x1 = 0.f, logit = -CUDART_INF_F;
            if (lane < 16){
                float2 xv = *(const float2*)(xf + (size_t)(b*NS + kj)*2);
                x0 = xv.x; x1 = xv.y;
                int mk = mask[b*NS + kj];
                logit = (mk != 0) ? -10000.f : (Sreg + x0*a0 + x1*a1)*0.125f;
            }
            float mx  = wmax(logit);
            float e   = (lane < 16) ? __expf(logit - mx) : 0.f;
            float den = wsum(e);
            float sx0 = wsum(e*x0);
            float sx1 = wsum(e*x1);
            float inv = 1.f/den;
            float attn = e*inv;
            float alpha = sx0*inv, beta = sx1*inv;

            float L0 = alpha*w0_s[lane]      + beta*w1_s[lane];
            float L1 = alpha*w0_s[32+lane]   + beta*w1_s[32+lane];
            float P0 = alpha*w0W_s[lane]     + beta*w1W_s[lane];
            float P1 = alpha*w0W_s[32+lane]  + beta*w1W_s[32+lane];
            #pragma unroll
            for (int k=0;k<16;k++){
                float ak = __shfl_sync(FULL, attn, k);
                L0 = fmaf(ak, rsp0[k], L0);
                L1 = fmaf(ak, rsp1[k], L1);
                P0 = fmaf(ak, rw0[k],  P0);
                P1 = fmaf(ak, rw1[k],  P1);
            }
            float sL  = wsum(L0 + L1);
            float sL2 = wsum(L0*L0 + L1*L1);

            // ---- global attention ----
            float gl = (lane < 24) ? g_gl[((size_t)n*16 + b)*24 + lane] : 0.f;
            int hbase = (lane/6)*6; if (hbase > 24) hbase = 24;
            float m6 = -CUDART_INF_F;
            #pragma unroll
            for (int tt=0;tt<6;tt++){ float v = __shfl_sync(FULL, gl, hbase+tt); m6 = fmaxf(m6, v); }
            float eg = __expf(gl - m6);
            float s6 = 0.f;
            #pragma unroll
            for (int tt=0;tt<6;tt++) s6 += __shfl_sync(FULL, eg, hbase+tt);
            float ga = eg / s6;
            // remap lane order (h*6+t) -> row order (t*4+h)
            int src = (lane < 24) ? ((lane & 3)*6 + (lane >> 2)) : 0;
            float gsh = __shfl_sync(FULL, ga, src);
            float gaR = (lane < 24) ? gsh : ((lane == 24) ? 1.f : 0.f);

            int rowi = (lane < 25) ? lane : 0;
            float sumg = wsum(gaR * sumv_s[b*25 + rowi]);

            float rowd = 0.f;
            #pragma unroll
            for (int i2=0;i2<25;i2++){
                float gv = __shfl_sync(FULL, gaR, i2);
                rowd = fmaf(gv, gram_s[(b*25 + rowi)*25 + i2], rowd);
            }
            float sumg2 = wsum(gaR * rowd);

            float Pg0 = 0.f, Pg1 = 0.f;
            #pragma unroll
            for (int i=0;i<25;i++){
                float gv = __shfl_sync(FULL, gaR, i);
                Pg0 = fmaf(gv, vgoW_s[(b*25+i)*64 + lane],      Pg0);
                Pg1 = fmaf(gv, vgoW_s[(b*25+i)*64 + 32 + lane], Pg1);
            }

            // ---- LN + MLP fold ----
            float mean = (sL + sumg)*(1.f/192.f);
            float var  = (sL2 + sumg2)*(1.f/192.f) - mean*mean;
            float rstd = rsqrtf(var + 1e-5f);
            float h0 = fmaf(rstd, (P0+Pg0) - mean*gcol_s[lane],    cadd_s[lane]);
            float h1 = fmaf(rstd, (P1+Pg1) - mean*gcol_s[32+lane], cadd_s[32+lane]);
            float gelu0 = 0.5f*h0*(1.f + erff(h0*0.70710678118654752f));
            float gelu1 = 0.5f*h1*(1.f + erff(h1*0.70710678118654752f));
            float pr = wsum(fmaf(gelu0, wm2_s[lane], gelu1*wm2_s[32+lane]));
            if (lane == 0){
                int mn = mask[b*NS + n];
                out[b*NS + n] = mn ? (pr + bm2v) : 0.f;
            }
        }
    }
}

// ------------------------- launch -------------------------
extern "C" void kernel_launch(void* const* d_in, const int* in_sizes, int n_in,
                              void* d_out, int out_size){
    const float* xf    = (const float*)d_in[0];
    const float* latent= (const float*)d_in[1];
    const float* pos   = (const float*)d_in[2];
    const float* femb  = (const float*)d_in[3];
    const float* Wnbr  = (const float*)d_in[4];
    const float* bnbr  = (const float*)d_in[5];
    const float* Wql   = (const float*)d_in[6];
    const float* bql   = (const float*)d_in[7];
    const float* Wlat  = (const float*)d_in[8];
    const float* blat  = (const float*)d_in[9];
    const float* Wlf   = (const float*)d_in[10];
    const float* blf   = (const float*)d_in[11];
    const float* Wqg   = (const float*)d_in[12];
    const float* bqg   = (const float*)d_in[13];
    const float* Wk    = (const float*)d_in[14];
    const float* bk    = (const float*)d_in[15];
    const float* Wv    = (const float*)d_in[16];
    const float* bv    = (const float*)d_in[17];
    const float* Wgo   = (const float*)d_in[18];
    const float* bgo   = (const float*)d_in[19];
    const float* lng   = (const float*)d_in[20];
    const float* lnb   = (const float*)d_in[21];
    const float* Wm1   = (const float*)d_in[22];
    const float* bm1   = (const float*)d_in[23];
    const float* Wm2   = (const float*)d_in[24];
    const float* bm2   = (const float*)d_in[25];
    const int* mask    = (const int*)d_in[26];
    const int* knn     = (const int*)d_in[27];
    const int* fid     = (const int*)d_in[28];
    float* out = (float*)d_out;

    cudaFuncSetAttribute(kA, cudaFuncAttributeMaxDynamicSharedMemorySize, 45056*4);
    cudaFuncSetAttribute(kF, cudaFuncAttributeMaxDynamicSharedMemorySize, 12672*4);
    cudaFuncSetAttribute(kG, cudaFuncAttributeMaxDynamicSharedMemorySize, 36448*4);

    k_consts<<<1,64>>>(Wnbr, lng, lnb, Wm1, bm1);
    kA<<<149,256,45056*4>>>(pos, femb, fid, Wnbr, bnbr, Wql, bql, Wqg, bqg, lng, Wm1);
    kD<<<dim3(6,16),128>>>(latent, femb, Wlat, blat, Wlf, blf, Wk, bk, Wv, bv, Wgo, bgo);
    kE<<<16,256,(3225+8192)*4>>>(lng, Wm1);
    kF<<<149,512,12672*4>>>();
    kG<<<149,512,36448*4>>>(xf, mask, knn, Wnbr, Wm2, bm2, out);
}